// round 3
// baseline (speedup 1.0000x reference)
#include <cuda_runtime.h>

#define NODES 20000
#define BATCH 32
#define FEAT  64
#define OUTD  64
#define EIG   16
#define CHUNKS 80
#define CHUNK  250   // NODES / CHUNKS exactly

// Scratch (device globals — no allocation allowed)
__device__ float g_zpart[CHUNKS * BATCH * FEAT * EIG]; // 10.5 MB partials
__device__ float g_z[BATCH * FEAT * EIG];              // 128 KB
__device__ float g_w[BATCH * OUTD * EIG];              // 128 KB

// ---------------------------------------------------------------------------
// Phase 1: z[b,i,f] = sum_m V[m,f] * x[b,m,i]   (split-K over node chunks)
// grid (BATCH, CHUNKS), 64 threads. Thread owns 4i x 4f register tile:
// 16 FFMA per (LDG.128 x + LDG.128 V). Unrolled with immediate offsets.
// ---------------------------------------------------------------------------
__global__ void __launch_bounds__(64) k_project(const float* __restrict__ x,
                                                const float* __restrict__ V) {
    const int b = blockIdx.x, c = blockIdx.y;
    const int t  = threadIdx.x;
    const int i4 = t & 15;   // i = 4*i4 .. 4*i4+3
    const int fq = t >> 4;   // f = 4*fq .. 4*fq+3  (0..3)

    const float* xp = x + (size_t)(b * NODES + c * CHUNK) * FEAT + 4 * i4;
    const float* vp = V + c * CHUNK * EIG + 4 * fq;

    float acc[4][4];
    #pragma unroll
    for (int a = 0; a < 4; ++a)
        #pragma unroll
        for (int d = 0; d < 4; ++d) acc[a][d] = 0.f;

    #pragma unroll 5
    for (int m = 0; m < CHUNK; ++m) {
        float4 x4 = *(const float4*)(xp + (size_t)m * FEAT);
        float4 v4 = *(const float4*)(vp + m * EIG);
        acc[0][0] += x4.x*v4.x; acc[0][1] += x4.x*v4.y; acc[0][2] += x4.x*v4.z; acc[0][3] += x4.x*v4.w;
        acc[1][0] += x4.y*v4.x; acc[1][1] += x4.y*v4.y; acc[1][2] += x4.y*v4.z; acc[1][3] += x4.y*v4.w;
        acc[2][0] += x4.z*v4.x; acc[2][1] += x4.z*v4.y; acc[2][2] += x4.z*v4.z; acc[2][3] += x4.z*v4.w;
        acc[3][0] += x4.w*v4.x; acc[3][1] += x4.w*v4.y; acc[3][2] += x4.w*v4.z; acc[3][3] += x4.w*v4.w;
    }

    float* dst = g_zpart + (size_t)(c * BATCH + b) * (FEAT * EIG) + (4 * i4) * EIG + 4 * fq;
    #pragma unroll
    for (int a = 0; a < 4; ++a)
        *(float4*)(dst + a * EIG) = make_float4(acc[a][0], acc[a][1], acc[a][2], acc[a][3]);
}

// ---------------------------------------------------------------------------
// Reduce chunk partials: z = sum_c zpart[c]   (L2-resident, ~10.5 MB read)
// ---------------------------------------------------------------------------
__global__ void k_reduce() {
    const int idx = blockIdx.x * blockDim.x + threadIdx.x;  // 32768 threads total
    float s = 0.f;
    #pragma unroll 16
    for (int c = 0; c < CHUNKS; ++c)
        s += g_zpart[c * (BATCH * FEAT * EIG) + idx];
    g_z[idx] = s;
}

// ---------------------------------------------------------------------------
// Phase 2: w[b,j,e] = sum_{i,f} G[j,i,e,f] * z[b,i,f]
// grid OUTD (block per j), 512 threads = 16 warps (warp = e).
// Lane l owns i = 2l, 2l+1; G slice (32 floats) cached in registers;
// warp-shuffle reduction. G read from DRAM exactly once.
// ---------------------------------------------------------------------------
__global__ void __launch_bounds__(512) k_filter(const float* __restrict__ G) {
    const int j = blockIdx.x;
    const int e = threadIdx.x >> 5;   // warp id = e (0..15)
    const int l = threadIdx.x & 31;   // lane -> i0 = 2l

    // G[j, i, e, f] offset: ((j*FEAT + i)*EIG + e)*EIG + f
    const float* Gp = G + ((size_t)(j * FEAT + 2 * l) * EIG + e) * EIG;
    float g0[16], g1[16];
    #pragma unroll
    for (int f4 = 0; f4 < 4; ++f4) {
        float4 a  = *(const float4*)(Gp + 4 * f4);
        float4 bb = *(const float4*)(Gp + EIG * EIG + 4 * f4);
        g0[4*f4+0]=a.x;  g0[4*f4+1]=a.y;  g0[4*f4+2]=a.z;  g0[4*f4+3]=a.w;
        g1[4*f4+0]=bb.x; g1[4*f4+1]=bb.y; g1[4*f4+2]=bb.z; g1[4*f4+3]=bb.w;
    }

    #pragma unroll 2
    for (int b = 0; b < BATCH; ++b) {
        const float* zb = g_z + b * (FEAT * EIG) + 2 * l * EIG;
        float acc = 0.f;
        #pragma unroll
        for (int f4 = 0; f4 < 4; ++f4) {
            float4 z0 = *(const float4*)(zb + 4 * f4);
            float4 z1 = *(const float4*)(zb + EIG + 4 * f4);
            acc += g0[4*f4+0]*z0.x + g0[4*f4+1]*z0.y + g0[4*f4+2]*z0.z + g0[4*f4+3]*z0.w;
            acc += g1[4*f4+0]*z1.x + g1[4*f4+1]*z1.y + g1[4*f4+2]*z1.z + g1[4*f4+3]*z1.w;
        }
        #pragma unroll
        for (int off = 16; off > 0; off >>= 1)
            acc += __shfl_down_sync(0xffffffffu, acc, off);
        if (l == 0) g_w[(b * OUTD + j) * EIG + e] = acc;
    }
}

// ---------------------------------------------------------------------------
// Phase 3: out[b,n,j] = sum_e V[n,e] * w[b,j,e]
// grid (ceil(NODES/128), BATCH), 256 threads. 8n x 4j register tile per
// thread: 3 LDS.128 per 32 FFMA.
// ---------------------------------------------------------------------------
#define NTILE 128
__global__ void __launch_bounds__(256) k_output(const float* __restrict__ V,
                                                float* __restrict__ out) {
    const int tile = blockIdx.x, b = blockIdx.y;
    const int t = threadIdx.x;   // 256
    __shared__ __align__(16) float wt[EIG][68];           // [e][j]
    __shared__ __align__(16) float vt[EIG][NTILE + 4];    // [e][n_local]

    const int n0 = tile * NTILE;

    // w[b][j][e] -> wt[e][j]
    for (int k = t; k < OUTD * EIG; k += 256)
        wt[k & 15][k >> 4] = g_w[b * (OUTD * EIG) + k];
    // V[n][e] -> vt[e][n - n0], zero-padded past NODES
    for (int k = t; k < NTILE * EIG; k += 256) {
        int nl = k >> 4, e = k & 15;
        int n = n0 + nl;
        vt[e][nl] = (n < NODES) ? V[n * EIG + e] : 0.f;
    }
    __syncthreads();

    const int j0  = (t & 15) * 4;
    const int nl0 = (t >> 4) * 8;
    float acc[8][4];
    #pragma unroll
    for (int a = 0; a < 8; ++a)
        #pragma unroll
        for (int d = 0; d < 4; ++d) acc[a][d] = 0.f;

    #pragma unroll
    for (int e = 0; e < EIG; ++e) {
        float4 va = *(const float4*)&vt[e][nl0];
        float4 vb = *(const float4*)&vt[e][nl0 + 4];
        float4 w4 = *(const float4*)&wt[e][j0];
        acc[0][0] += va.x*w4.x; acc[0][1] += va.x*w4.y; acc[0][2] += va.x*w4.z; acc[0][3] += va.x*w4.w;
        acc[1][0] += va.y*w4.x; acc[1][1] += va.y*w4.y; acc[1][2] += va.y*w4.z; acc[1][3] += va.y*w4.w;
        acc[2][0] += va.z*w4.x; acc[2][1] += va.z*w4.y; acc[2][2] += va.z*w4.z; acc[2][3] += va.z*w4.w;
        acc[3][0] += va.w*w4.x; acc[3][1] += va.w*w4.y; acc[3][2] += va.w*w4.z; acc[3][3] += va.w*w4.w;
        acc[4][0] += vb.x*w4.x; acc[4][1] += vb.x*w4.y; acc[4][2] += vb.x*w4.z; acc[4][3] += vb.x*w4.w;
        acc[5][0] += vb.y*w4.x; acc[5][1] += vb.y*w4.y; acc[5][2] += vb.y*w4.z; acc[5][3] += vb.y*w4.w;
        acc[6][0] += vb.z*w4.x; acc[6][1] += vb.z*w4.y; acc[6][2] += vb.z*w4.z; acc[6][3] += vb.z*w4.w;
        acc[7][0] += vb.w*w4.x; acc[7][1] += vb.w*w4.y; acc[7][2] += vb.w*w4.z; acc[7][3] += vb.w*w4.w;
    }

    float* ob = out + ((size_t)b * NODES + n0 + nl0) * OUTD + j0;
    #pragma unroll
    for (int ni = 0; ni < 8; ++ni) {
        if (n0 + nl0 + ni < NODES)
            *(float4*)(ob + (size_t)ni * OUTD) =
                make_float4(acc[ni][0], acc[ni][1], acc[ni][2], acc[ni][3]);
    }
}

extern "C" void kernel_launch(void* const* d_in, const int* in_sizes, int n_in,
                              void* d_out, int out_size) {
    const float* x = (const float*)d_in[0];   // (32, 20000, 64)
    const float* V = (const float*)d_in[1];   // (20000, 16)
    const float* G = (const float*)d_in[2];   // (64, 64, 16, 16)
    float* out = (float*)d_out;               // (32, 20000, 64)

    k_project<<<dim3(BATCH, CHUNKS), 64>>>(x, V);
    k_reduce<<<32, 1024>>>();
    k_filter<<<OUTD, 512>>>(G);
    k_output<<<dim3((NODES + NTILE - 1) / NTILE, BATCH), 256>>>(V, out);
}

// round 4
// speedup vs baseline: 1.0460x; 1.0460x over previous
#include <cuda_runtime.h>

#define NODES 20000
#define BATCH 32
#define FEAT  64
#define OUTD  64
#define EIG   16
#define CBLK   80     // chunk-blocks in grid
#define CHUNK  125    // m per half-chunk
#define CHUNKS_EFF (CBLK * 2)   // 160 partials

// Scratch (device globals — no allocation allowed)
__device__ float g_zpart[CHUNKS_EFF * BATCH * FEAT * EIG]; // 21 MB partials
__device__ float g_z[BATCH * FEAT * EIG];                  // 128 KB
__device__ float g_w[BATCH * OUTD * EIG];                  // 128 KB

// ---------------------------------------------------------------------------
// Phase 1: z[b,i,f] = sum_m V[m,f] * x[b,m,i]   (split-K over node chunks)
// grid (BATCH, CBLK), 128 threads = 4 warps. Warps 0-1 take m-half 0,
// warps 2-3 take m-half 1 (disjoint 125-node streams -> 2x load streams/SM
// vs R3's 64-thread blocks; 68 warps/SM). Thread owns 4i x 4f register tile:
// 16 FFMA per (LDG.128 x + LDG.128 V).
// ---------------------------------------------------------------------------
__global__ void __launch_bounds__(128) k_project(const float* __restrict__ x,
                                                 const float* __restrict__ V) {
    const int b = blockIdx.x, c = blockIdx.y;
    const int t  = threadIdx.x;
    const int i4 = t & 15;          // i = 4*i4 .. 4*i4+3
    const int fq = (t >> 4) & 3;    // f = 4*fq .. 4*fq+3
    const int mh = t >> 6;          // m-half 0/1
    const int ceff = c * 2 + mh;
    const int m0 = ceff * CHUNK;

    const float* xp = x + (size_t)(b * NODES + m0) * FEAT + 4 * i4;
    const float* vp = V + m0 * EIG + 4 * fq;

    float acc[4][4];
    #pragma unroll
    for (int a = 0; a < 4; ++a)
        #pragma unroll
        for (int d = 0; d < 4; ++d) acc[a][d] = 0.f;

    #pragma unroll 5
    for (int m = 0; m < CHUNK; ++m) {
        float4 x4 = *(const float4*)(xp + (size_t)m * FEAT);
        float4 v4 = *(const float4*)(vp + m * EIG);
        acc[0][0] += x4.x*v4.x; acc[0][1] += x4.x*v4.y; acc[0][2] += x4.x*v4.z; acc[0][3] += x4.x*v4.w;
        acc[1][0] += x4.y*v4.x; acc[1][1] += x4.y*v4.y; acc[1][2] += x4.y*v4.z; acc[1][3] += x4.y*v4.w;
        acc[2][0] += x4.z*v4.x; acc[2][1] += x4.z*v4.y; acc[2][2] += x4.z*v4.z; acc[2][3] += x4.z*v4.w;
        acc[3][0] += x4.w*v4.x; acc[3][1] += x4.w*v4.y; acc[3][2] += x4.w*v4.z; acc[3][3] += x4.w*v4.w;
    }

    float* dst = g_zpart + (size_t)(ceff * BATCH + b) * (FEAT * EIG) + (4 * i4) * EIG + 4 * fq;
    #pragma unroll
    for (int a = 0; a < 4; ++a)
        *(float4*)(dst + a * EIG) = make_float4(acc[a][0], acc[a][1], acc[a][2], acc[a][3]);
}

// ---------------------------------------------------------------------------
// Reduce chunk partials: z = sum_c zpart[c]   (L2-resident, ~21 MB read)
// ---------------------------------------------------------------------------
__global__ void k_reduce() {
    const int idx = blockIdx.x * blockDim.x + threadIdx.x;  // 32768 threads total
    float s = 0.f;
    #pragma unroll 16
    for (int c = 0; c < CHUNKS_EFF; ++c)
        s += g_zpart[c * (BATCH * FEAT * EIG) + idx];
    g_z[idx] = s;
}

// ---------------------------------------------------------------------------
// Phase 2: w[b,j,e] = sum_{i,f} G[j,i,e,f] * z[b,i,f]
// grid OUTD (block per j), 512 threads = 16 warps (warp = e).
// Lane l owns i = 2l, 2l+1; G slice (32 floats) cached in registers;
// warp-shuffle reduction. G read from DRAM exactly once.
// ---------------------------------------------------------------------------
__global__ void __launch_bounds__(512) k_filter(const float* __restrict__ G) {
    const int j = blockIdx.x;
    const int e = threadIdx.x >> 5;   // warp id = e (0..15)
    const int l = threadIdx.x & 31;   // lane -> i0 = 2l

    // G[j, i, e, f] offset: ((j*FEAT + i)*EIG + e)*EIG + f
    const float* Gp = G + ((size_t)(j * FEAT + 2 * l) * EIG + e) * EIG;
    float g0[16], g1[16];
    #pragma unroll
    for (int f4 = 0; f4 < 4; ++f4) {
        float4 a  = *(const float4*)(Gp + 4 * f4);
        float4 bb = *(const float4*)(Gp + EIG * EIG + 4 * f4);
        g0[4*f4+0]=a.x;  g0[4*f4+1]=a.y;  g0[4*f4+2]=a.z;  g0[4*f4+3]=a.w;
        g1[4*f4+0]=bb.x; g1[4*f4+1]=bb.y; g1[4*f4+2]=bb.z; g1[4*f4+3]=bb.w;
    }

    #pragma unroll 2
    for (int b = 0; b < BATCH; ++b) {
        const float* zb = g_z + b * (FEAT * EIG) + 2 * l * EIG;
        float acc = 0.f;
        #pragma unroll
        for (int f4 = 0; f4 < 4; ++f4) {
            float4 z0 = *(const float4*)(zb + 4 * f4);
            float4 z1 = *(const float4*)(zb + EIG + 4 * f4);
            acc += g0[4*f4+0]*z0.x + g0[4*f4+1]*z0.y + g0[4*f4+2]*z0.z + g0[4*f4+3]*z0.w;
            acc += g1[4*f4+0]*z1.x + g1[4*f4+1]*z1.y + g1[4*f4+2]*z1.z + g1[4*f4+3]*z1.w;
        }
        #pragma unroll
        for (int off = 16; off > 0; off >>= 1)
            acc += __shfl_down_sync(0xffffffffu, acc, off);
        if (l == 0) g_w[(b * OUTD + j) * EIG + e] = acc;
    }
}

// ---------------------------------------------------------------------------
// Phase 3: out[b,n,j] = sum_e V[n,e] * w[b,j,e]
// R1-proven config: grid (ceil(NODES/64), BATCH), 256 threads, 4n x 4j
// register tile (31 regs, occ ~92%).
// ---------------------------------------------------------------------------
#define NTILE 64
__global__ void __launch_bounds__(256) k_output(const float* __restrict__ V,
                                                float* __restrict__ out) {
    const int tile = blockIdx.x, b = blockIdx.y;
    const int t = threadIdx.x;   // 256
    __shared__ __align__(16) float wt[EIG][68];
    __shared__ __align__(16) float vt[EIG][68];

    const int n0 = tile * NTILE;

    // w[b][j][e] -> wt[e][j]
    for (int k = t; k < OUTD * EIG; k += 256)
        wt[k & 15][k >> 4] = g_w[b * (OUTD * EIG) + k];
    // V[n][e] -> vt[e][n - n0], zero-padded past NODES
    for (int k = t; k < NTILE * EIG; k += 256) {
        int nl = k >> 4, e = k & 15;
        int n = n0 + nl;
        vt[e][nl] = (n < NODES) ? V[n * EIG + e] : 0.f;
    }
    __syncthreads();

    const int j0  = (t & 15) * 4;
    const int nl0 = (t >> 4) * 4;
    float acc[4][4];
    #pragma unroll
    for (int a = 0; a < 4; ++a)
        #pragma unroll
        for (int c = 0; c < 4; ++c) acc[a][c] = 0.f;

    #pragma unroll
    for (int e = 0; e < EIG; ++e) {
        float4 v4 = *(const float4*)&vt[e][nl0];
        float4 w4 = *(const float4*)&wt[e][j0];
        acc[0][0] += v4.x*w4.x; acc[0][1] += v4.x*w4.y; acc[0][2] += v4.x*w4.z; acc[0][3] += v4.x*w4.w;
        acc[1][0] += v4.y*w4.x; acc[1][1] += v4.y*w4.y; acc[1][2] += v4.y*w4.z; acc[1][3] += v4.y*w4.w;
        acc[2][0] += v4.z*w4.x; acc[2][1] += v4.z*w4.y; acc[2][2] += v4.z*w4.z; acc[2][3] += v4.z*w4.w;
        acc[3][0] += v4.w*w4.x; acc[3][1] += v4.w*w4.y; acc[3][2] += v4.w*w4.z; acc[3][3] += v4.w*w4.w;
    }

    float* ob = out + ((size_t)b * NODES + n0 + nl0) * OUTD + j0;
    #pragma unroll
    for (int ni = 0; ni < 4; ++ni) {
        if (n0 + nl0 + ni < NODES)
            *(float4*)(ob + (size_t)ni * OUTD) =
                make_float4(acc[ni][0], acc[ni][1], acc[ni][2], acc[ni][3]);
    }
}

extern "C" void kernel_launch(void* const* d_in, const int* in_sizes, int n_in,
                              void* d_out, int out_size) {
    const float* x = (const float*)d_in[0];   // (32, 20000, 64)
    const float* V = (const float*)d_in[1];   // (20000, 16)
    const float* G = (const float*)d_in[2];   // (64, 64, 16, 16)
    float* out = (float*)d_out;               // (32, 20000, 64)

    k_project<<<dim3(BATCH, CBLK), 128>>>(x, V);
    k_reduce<<<32, 1024>>>();
    k_filter<<<OUTD, 512>>>(G);
    k_output<<<dim3((NODES + NTILE - 1) / NTILE, BATCH), 256>>>(V, out);
}